// round 11
// baseline (speedup 1.0000x reference)
#include <cuda_runtime.h>
#include <math.h>

#define BB 32
#define CC 256
#define HH 64
#define WW 64
#define EPS 1e-5f
#define NCG 16   // number of C-group blocks contributing to hw pool
#define TC 16

// ---- scratch (static device globals; no cudaMalloc anywhere) ----
__device__ float g_hw_part_max[NCG*BB*HH*WW];  // [cg][B][H][W] partials
__device__ float g_hw_part_sum[NCG*BB*HH*WW];
__device__ float g_pool_hw_max[BB*HH*WW];      // [B][H][W] reduced
__device__ float g_pool_hw_sum[BB*HH*WW];
__device__ float g_pool_cw_max[BB*CC*WW];      // [B][C][W]
__device__ float g_pool_cw_sum[BB*CC*WW];
__device__ float g_pool_ch_max[BB*HH*CC];      // [B][H][C]
__device__ float g_pool_ch_sum[BB*HH*CC];
__device__ float g_gate_hw[BB*HH*WW];          // [B][H][W]
__device__ float g_gate_cw[BB*CC*WW];          // [B][C][W]
__device__ float g_gate_ch[BB*HH*CC];          // [B][H][C]
__device__ unsigned int g_img_ctr[BB];         // zero-initialized; reset in-kernel

__device__ __forceinline__ float4 f4max(float4 a, float4 b) {
    return make_float4(fmaxf(a.x,b.x), fmaxf(a.y,b.y), fmaxf(a.z,b.z), fmaxf(a.w,b.w));
}
__device__ __forceinline__ float4 f4add(float4 a, float4 b) {
    return make_float4(a.x+b.x, a.y+b.y, a.z+b.z, a.w+b.w);
}

// ---- kernel 1: fused BN + triple (max,sum) pooling ----
// grid (C/TC, B), 256 threads = 8 warps. Warp w owns rows [8w, 8w+8).
// Lane: sub = lane>>4 (row parity per 2-row step), q = lane&15 (float4 pos in W).
// The LAST block to finish for an image folds the 16 hw partial planes itself.
__global__ __launch_bounds__(256) void pool_kernel(
    const float* __restrict__ x,
    const float* __restrict__ gamma, const float* __restrict__ beta,
    const float* __restrict__ mean,  const float* __restrict__ var)
{
    __shared__ float s_scale[TC], s_shift[TC];
    // ch staging: [buf][row 0..63][q 0..15], padded row stride 20 floats
    __shared__ float s_ch_max[2][64][20];
    __shared__ float s_ch_sum[2][64][20];
    // cw staging: [buf][rowgroup 0..15 = warp*2+sub][w 0..63], padded stride 68
    __shared__ float s_cw_max[2][16][68];
    __shared__ float s_cw_sum[2][16][68];
    // ch output staging: [h][local channel], pad 17 (conflict-free)
    __shared__ float s_cho_max[64][17];
    __shared__ float s_cho_sum[64][17];
    __shared__ unsigned int s_last;

    const int b    = blockIdx.y;
    const int cg   = blockIdx.x;
    const int c0   = cg * TC;
    const int tid  = threadIdx.x;
    const int w    = tid >> 5;
    const int lane = tid & 31;
    const int sub  = lane >> 4;
    const int q    = lane & 15;

    if (tid < TC) {
        float sc = __ldg(&gamma[c0+tid]) * rsqrtf(__ldg(&var[c0+tid]) + EPS);
        s_scale[tid] = sc;
        s_shift[tid] = __ldg(&beta[c0+tid]) - __ldg(&mean[c0+tid]) * sc;
    }
    __syncthreads();

    float4 hmax[4], hsum[4];
    #pragma unroll
    for (int i = 0; i < 4; i++) {
        hmax[i] = make_float4(-INFINITY,-INFINITY,-INFINITY,-INFINITY);
        hsum[i] = make_float4(0.f,0.f,0.f,0.f);
    }

    const float* xb = x + ((size_t)b*CC + c0)*HH*WW;
    int off[4];
    #pragma unroll
    for (int hj = 0; hj < 4; hj++) off[hj] = (w*8 + hj*2 + sub)*16 + q;

    // prefetch channel 0 (streaming: no reuse of x in L2)
    float4 v[4];
    {
        const float4* p = (const float4*)xb;
        #pragma unroll
        for (int hj = 0; hj < 4; hj++) v[hj] = __ldcs(p + off[hj]);
    }

    for (int ci = 0; ci < TC; ci++) {
        float4 cur[4];
        #pragma unroll
        for (int hj = 0; hj < 4; hj++) cur[hj] = v[hj];
        if (ci + 1 < TC) {
            const float4* p = (const float4*)(xb + (size_t)(ci+1)*HH*WW);
            #pragma unroll
            for (int hj = 0; hj < 4; hj++) v[hj] = __ldcs(p + off[hj]);
        }

        const float sc = s_scale[ci], sh = s_shift[ci];
        const int buf = ci & 1;
        float4 cmax = make_float4(-INFINITY,-INFINITY,-INFINITY,-INFINITY);
        float4 csum = make_float4(0.f,0.f,0.f,0.f);

        #pragma unroll
        for (int hj = 0; hj < 4; hj++) {
            float4 xn;
            xn.x = fmaf(cur[hj].x, sc, sh); xn.y = fmaf(cur[hj].y, sc, sh);
            xn.z = fmaf(cur[hj].z, sc, sh); xn.w = fmaf(cur[hj].w, sc, sh);

            hmax[hj] = f4max(hmax[hj], xn); hsum[hj] = f4add(hsum[hj], xn);
            cmax     = f4max(cmax, xn);     csum     = f4add(csum, xn);

            // ch partial for (row, q): horizontal fold of this thread's 4 W values
            const int row = w*8 + hj*2 + sub;
            s_ch_max[buf][row][q] = fmaxf(fmaxf(xn.x, xn.y), fmaxf(xn.z, xn.w));
            s_ch_sum[buf][row][q] = (xn.x + xn.y) + (xn.z + xn.w);
        }

        // cw partial for this (warp,sub) row-group
        *(float4*)&s_cw_max[buf][w*2 + sub][q*4] = cmax;
        *(float4*)&s_cw_sum[buf][w*2 + sub][q*4] = csum;

        // every 2 channels: fold staged partials with all 256 threads
        if (buf == 1) {
            __syncthreads();
            if (tid < 128) {
                // ch: (cb, h) -> fold 16 q partials -> smem output staging
                const int cb = tid & 1;
                const int h  = tid >> 1;
                float4 m0 = *(const float4*)&s_ch_max[cb][h][0];
                float4 m1 = *(const float4*)&s_ch_max[cb][h][4];
                float4 m2 = *(const float4*)&s_ch_max[cb][h][8];
                float4 m3 = *(const float4*)&s_ch_max[cb][h][12];
                float4 s0 = *(const float4*)&s_ch_sum[cb][h][0];
                float4 s1 = *(const float4*)&s_ch_sum[cb][h][4];
                float4 s2 = *(const float4*)&s_ch_sum[cb][h][8];
                float4 s3 = *(const float4*)&s_ch_sum[cb][h][12];
                float4 mm = f4max(f4max(m0, m1), f4max(m2, m3));
                float4 ss = f4add(f4add(s0, s1), f4add(s2, s3));
                const int cl = ci - 1 + cb;            // local channel 0..15
                s_cho_max[h][cl] = fmaxf(fmaxf(mm.x, mm.y), fmaxf(mm.z, mm.w));
                s_cho_sum[h][cl] = (ss.x + ss.y) + (ss.z + ss.w);
            } else {
                // cw: (cb, wcol) -> fold 16 row-group partials -> coalesced STG
                const int tt = tid - 128;
                const int cb = tt & 1;
                const int wc = tt >> 1;
                float m = s_cw_max[cb][0][wc];
                float s = s_cw_sum[cb][0][wc];
                #pragma unroll
                for (int k = 1; k < 16; k++) {
                    m = fmaxf(m, s_cw_max[cb][k][wc]);
                    s += s_cw_sum[cb][k][wc];
                }
                size_t idx = ((size_t)b*CC + (c0 + ci - 1 + cb))*WW + wc;
                g_pool_cw_max[idx] = m;
                g_pool_cw_sum[idx] = s;
            }
            __syncthreads();
        }
    }

    // ch writeout: coalesced float4 stores along C (16 channels per row)
    {
        const int hrow = tid >> 2;      // 0..63
        const int f    = tid & 3;       // 0..3 -> channels 4f..4f+3
        float4 mo, so;
        mo.x = s_cho_max[hrow][4*f+0]; mo.y = s_cho_max[hrow][4*f+1];
        mo.z = s_cho_max[hrow][4*f+2]; mo.w = s_cho_max[hrow][4*f+3];
        so.x = s_cho_sum[hrow][4*f+0]; so.y = s_cho_sum[hrow][4*f+1];
        so.z = s_cho_sum[hrow][4*f+2]; so.w = s_cho_sum[hrow][4*f+3];
        size_t idx4 = (((size_t)b*HH + hrow)*CC + c0)/4 + f;
        ((float4*)g_pool_ch_max)[idx4] = mo;
        ((float4*)g_pool_ch_sum)[idx4] = so;
    }

    // hw: plain vector stores of this C-group's partials (stay L2-resident)
    const int IMG4 = HH*WW/4;   // 1024 float4 per image plane
    {
        float4* pm4 = (float4*)g_hw_part_max + (size_t)cg * (BB*IMG4);
        float4* ps4 = (float4*)g_hw_part_sum + (size_t)cg * (BB*IMG4);
        #pragma unroll
        for (int hj = 0; hj < 4; hj++) {
            const int h = w*8 + hj*2 + sub;
            size_t idx = ((size_t)b*HH + h)*(WW/4) + q;
            pm4[idx] = hmax[hj];
            ps4[idx] = hsum[hj];
        }
    }

    // last block for this image folds the 16 hw partial planes (L2-hot)
    __threadfence();
    if (tid == 0)
        s_last = (atomicAdd(&g_img_ctr[b], 1u) == (unsigned)(NCG - 1)) ? 1u : 0u;
    __syncthreads();
    if (s_last) {
        const int STRIDE = BB*IMG4;
        const float4* pm4 = (const float4*)g_hw_part_max + (size_t)b*IMG4;
        const float4* ps4 = (const float4*)g_hw_part_sum + (size_t)b*IMG4;
        float4* om4 = (float4*)g_pool_hw_max + (size_t)b*IMG4;
        float4* os4 = (float4*)g_pool_hw_sum + (size_t)b*IMG4;
        for (int i = tid; i < IMG4; i += 256) {
            float4 m = pm4[i];
            float4 s = ps4[i];
            #pragma unroll
            for (int g = 1; g < NCG; g++) {
                m = f4max(m, pm4[(size_t)g*STRIDE + i]);
                s = f4add(s, ps4[(size_t)g*STRIDE + i]);
            }
            om4[i] = m;
            os4[i] = s;
        }
        if (tid == 0) g_img_ctr[b] = 0u;   // reset for next graph replay
    }
}

// ---- kernel 2: ALL three 7x7 conv gates, fused + smem tiled ----
__global__ __launch_bounds__(256) void conv_gate_fused_kernel(
    const float* __restrict__ hw_w, const float* __restrict__ hw_g,
    const float* __restrict__ hw_b, const float* __restrict__ hw_m,
    const float* __restrict__ hw_v,
    const float* __restrict__ cw_w, const float* __restrict__ cw_g,
    const float* __restrict__ cw_b, const float* __restrict__ cw_m,
    const float* __restrict__ cw_v,
    const float* __restrict__ ch_w, const float* __restrict__ ch_g,
    const float* __restrict__ ch_b, const float* __restrict__ ch_m,
    const float* __restrict__ ch_v)
{
    __shared__ float smax[38*39];
    __shared__ float ssum[38*39];
    __shared__ float swt[98];
    __shared__ float sbn[2];

    const int bid = blockIdx.x;
    const int tid = threadIdx.x;

    int R, S, bImg, ti, tj;
    const float *pm, *ps, *wts, *g1, *b1, *m1, *v1;
    float *gate;
    float invN;
    if (bid < 128) {
        R = HH; S = WW; bImg = bid >> 2; int t = bid & 3;
        ti = (t >> 1) * 32; tj = (t & 1) * 32;
        pm = g_pool_hw_max; ps = g_pool_hw_sum; gate = g_gate_hw;
        wts = hw_w; g1 = hw_g; b1 = hw_b; m1 = hw_m; v1 = hw_v; invN = 1.f/256.f;
    } else if (bid < 640) {
        R = CC; S = WW; int t = bid - 128; bImg = t >> 4; t &= 15;
        ti = (t >> 1) * 32; tj = (t & 1) * 32;
        pm = g_pool_cw_max; ps = g_pool_cw_sum; gate = g_gate_cw;
        wts = cw_w; g1 = cw_g; b1 = cw_b; m1 = cw_m; v1 = cw_v; invN = 1.f/64.f;
    } else {
        R = HH; S = CC; int t = bid - 640; bImg = t >> 4; t &= 15;
        ti = (t >> 3) * 32; tj = (t & 7) * 32;
        pm = g_pool_ch_max; ps = g_pool_ch_sum; gate = g_gate_ch;
        wts = ch_w; g1 = ch_g; b1 = ch_b; m1 = ch_m; v1 = ch_v; invN = 1.f/64.f;
    }
    pm += (size_t)bImg * R * S;
    ps += (size_t)bImg * R * S;
    gate += (size_t)bImg * R * S;

    for (int i = tid; i < 38*38; i += 256) {
        int li = i / 38, lj = i - li*38;
        int gi = ti + li - 3, gj = tj + lj - 3;
        bool ok = (gi >= 0) & (gi < R) & (gj >= 0) & (gj < S);
        size_t p = (size_t)gi * S + gj;
        smax[li*39 + lj] = ok ? __ldg(&pm[p]) : 0.f;
        ssum[li*39 + lj] = ok ? __ldg(&ps[p]) : 0.f;
    }
    if (tid < 98) swt[tid] = __ldg(&wts[tid]) * (tid >= 49 ? invN : 1.f);
    if (tid == 98) {
        float s = __ldg(&g1[0]) * rsqrtf(__ldg(&v1[0]) + EPS);
        sbn[0] = s;
        sbn[1] = __ldg(&b1[0]) - __ldg(&m1[0]) * s;
    }
    __syncthreads();

    const int ty = tid >> 3;
    const int tx = (tid & 7) * 4;
    float acc0 = 0.f, acc1 = 0.f, acc2 = 0.f, acc3 = 0.f;

    #pragma unroll
    for (int di = 0; di < 7; di++) {
        float rm[10], rs[10];
        const int rowb = (ty + di) * 39 + tx;
        #pragma unroll
        for (int k = 0; k < 10; k++) {
            rm[k] = smax[rowb + k];
            rs[k] = ssum[rowb + k];
        }
        #pragma unroll
        for (int dj = 0; dj < 7; dj++) {
            const float w1 = swt[di*7 + dj];
            const float w2 = swt[49 + di*7 + dj];
            acc0 = fmaf(rm[dj+0], w1, acc0); acc0 = fmaf(rs[dj+0], w2, acc0);
            acc1 = fmaf(rm[dj+1], w1, acc1); acc1 = fmaf(rs[dj+1], w2, acc1);
            acc2 = fmaf(rm[dj+2], w1, acc2); acc2 = fmaf(rs[dj+2], w2, acc2);
            acc3 = fmaf(rm[dj+3], w1, acc3); acc3 = fmaf(rs[dj+3], w2, acc3);
        }
    }

    const float s = sbn[0], t0 = sbn[1];
    float4 o;
    o.x = 1.f / (1.f + expf(-fmaf(acc0, s, t0)));
    o.y = 1.f / (1.f + expf(-fmaf(acc1, s, t0)));
    o.z = 1.f / (1.f + expf(-fmaf(acc2, s, t0)));
    o.w = 1.f / (1.f + expf(-fmaf(acc3, s, t0)));
    *(float4*)(gate + (size_t)(ti + ty) * S + (tj + tx)) = o;
}

// ---- kernel 3: out = x + (1/3)(g_hw + g_cw + g_ch) * relu(BN(x)) ----
__global__ __launch_bounds__(256) void final_kernel(
    const float* __restrict__ x,
    const float* __restrict__ gamma, const float* __restrict__ beta,
    const float* __restrict__ mean,  const float* __restrict__ var,
    float* __restrict__ out)
{
    size_t t = (size_t)blockIdx.x * blockDim.x + threadIdx.x;
    int w4 = (int)(t & 15);
    int h  = (int)((t >> 4) & 63);
    int c  = (int)((t >> 10) & 255);
    int b  = (int)(t >> 18);

    float4 xv = __ldcs(&((const float4*)x)[t]);   // streaming read

    float sc = __ldg(&gamma[c]) * rsqrtf(__ldg(&var[c]) + EPS);
    float sh = __ldg(&beta[c]) - __ldg(&mean[c]) * sc;

    float4 ghw = __ldg(&((const float4*)g_gate_hw)[((size_t)b*HH + h)*(WW/4) + w4]);
    float4 gcw = __ldg(&((const float4*)g_gate_cw)[((size_t)b*CC + c)*(WW/4) + w4]);
    float  gch = __ldg(&g_gate_ch[((size_t)b*HH + h)*CC + c]);

    const float k = 1.f / 3.f;
    float4 o;
    { float xn = fmaf(xv.x, sc, sh); float l = fmaxf(xn, 0.f);
      o.x = fmaf(k * (ghw.x + gcw.x + gch), l, xv.x); }
    { float xn = fmaf(xv.y, sc, sh); float l = fmaxf(xn, 0.f);
      o.y = fmaf(k * (ghw.y + gcw.y + gch), l, xv.y); }
    { float xn = fmaf(xv.z, sc, sh); float l = fmaxf(xn, 0.f);
      o.z = fmaf(k * (ghw.z + gcw.z + gch), l, xv.z); }
    { float xn = fmaf(xv.w, sc, sh); float l = fmaxf(xn, 0.f);
      o.w = fmaf(k * (ghw.w + gcw.w + gch), l, xv.w); }
    __stcs(&((float4*)out)[t], o);                // streaming write
}

extern "C" void kernel_launch(void* const* d_in, const int* in_sizes, int n_in,
                              void* d_out, int out_size) {
    const float* x     = (const float*)d_in[0];
    const float* gamma = (const float*)d_in[1];
    const float* beta  = (const float*)d_in[2];
    const float* mean  = (const float*)d_in[3];
    const float* var   = (const float*)d_in[4];
    const float* hw_w  = (const float*)d_in[5];
    const float* hw_g  = (const float*)d_in[6];
    const float* hw_b  = (const float*)d_in[7];
    const float* hw_m  = (const float*)d_in[8];
    const float* hw_v  = (const float*)d_in[9];
    const float* cw_w  = (const float*)d_in[10];
    const float* cw_g  = (const float*)d_in[11];
    const float* cw_b  = (const float*)d_in[12];
    const float* cw_m  = (const float*)d_in[13];
    const float* cw_v  = (const float*)d_in[14];
    const float* ch_w  = (const float*)d_in[15];
    const float* ch_g  = (const float*)d_in[16];
    const float* ch_b  = (const float*)d_in[17];
    const float* ch_m  = (const float*)d_in[18];
    const float* ch_v  = (const float*)d_in[19];
    float* out = (float*)d_out;

    // 1) fused BN + triple pooling (last block per image folds hw partials)
    dim3 pg(CC/TC, BB);
    pool_kernel<<<pg, 256>>>(x, gamma, beta, mean, var);

    // 2) all three conv gates in one launch
    conv_gate_fused_kernel<<<1152, 256>>>(
        hw_w, hw_g, hw_b, hw_m, hw_v,
        cw_w, cw_g, cw_b, cw_m, cw_v,
        ch_w, ch_g, ch_b, ch_m, ch_v);

    // 3) final fused elementwise
    size_t total4 = (size_t)BB*CC*HH*WW/4;
    final_kernel<<<(unsigned)(total4/256), 256>>>(
        x, gamma, beta, mean, var, out);
}

// round 12
// speedup vs baseline: 1.0949x; 1.0949x over previous
#include <cuda_runtime.h>
#include <math.h>

#define BB 32
#define CC 256
#define HH 64
#define WW 64
#define EPS 1e-5f
#define NCG 16   // number of C-group blocks contributing to hw pool
#define TC 16

// ---- scratch (static device globals; no cudaMalloc anywhere) ----
__device__ float g_hw_part_max[NCG*BB*HH*WW];  // [cg][B][H][W] partials
__device__ float g_hw_part_sum[NCG*BB*HH*WW];
__device__ float g_pool_hw_max[BB*HH*WW];      // [B][H][W] reduced
__device__ float g_pool_hw_sum[BB*HH*WW];
__device__ float g_pool_cw_max[BB*CC*WW];      // [B][C][W]
__device__ float g_pool_cw_sum[BB*CC*WW];
__device__ float g_pool_ch_max[BB*HH*CC];      // [B][H][C]
__device__ float g_pool_ch_sum[BB*HH*CC];
__device__ float g_gate_hw[BB*HH*WW];          // [B][H][W]
__device__ float g_gate_cw[BB*CC*WW];          // [B][C][W]
__device__ float g_gate_ch[BB*HH*CC];          // [B][H][C]

__device__ __forceinline__ float4 f4max(float4 a, float4 b) {
    return make_float4(fmaxf(a.x,b.x), fmaxf(a.y,b.y), fmaxf(a.z,b.z), fmaxf(a.w,b.w));
}
__device__ __forceinline__ float4 f4add(float4 a, float4 b) {
    return make_float4(a.x+b.x, a.y+b.y, a.z+b.z, a.w+b.w);
}

// ---- kernel 1: fused BN + triple (max,sum) pooling ----
// grid (C/TC, B), 256 threads = 8 warps, 4 blocks/SM (one wave).
// Lane: sub = lane>>4 (row parity per 2-row step), q = lane&15 (float4 pos in W).
__global__ __launch_bounds__(256, 4) void pool_kernel(
    const float* __restrict__ x,
    const float* __restrict__ gamma, const float* __restrict__ beta,
    const float* __restrict__ mean,  const float* __restrict__ var)
{
    __shared__ float s_scale[TC], s_shift[TC];
    // ch staging: [buf][row 0..63][q 0..15], padded row stride 20 floats
    __shared__ float s_ch_max[2][64][20];
    __shared__ float s_ch_sum[2][64][20];
    // cw staging: [buf][rowgroup 0..15 = warp*2+sub][w 0..63], padded stride 68
    __shared__ float s_cw_max[2][16][68];
    __shared__ float s_cw_sum[2][16][68];
    // ch output staging: [h][local channel], pad 17 (conflict-free)
    __shared__ float s_cho_max[64][17];
    __shared__ float s_cho_sum[64][17];

    const int b    = blockIdx.y;
    const int cg   = blockIdx.x;
    const int c0   = cg * TC;
    const int tid  = threadIdx.x;
    const int w    = tid >> 5;
    const int lane = tid & 31;
    const int sub  = lane >> 4;
    const int q    = lane & 15;

    if (tid < TC) {
        float sc = __ldg(&gamma[c0+tid]) * rsqrtf(__ldg(&var[c0+tid]) + EPS);
        s_scale[tid] = sc;
        s_shift[tid] = __ldg(&beta[c0+tid]) - __ldg(&mean[c0+tid]) * sc;
    }
    __syncthreads();

    float4 hmax[4], hsum[4];
    #pragma unroll
    for (int i = 0; i < 4; i++) {
        hmax[i] = make_float4(-INFINITY,-INFINITY,-INFINITY,-INFINITY);
        hsum[i] = make_float4(0.f,0.f,0.f,0.f);
    }

    const float* xb = x + ((size_t)b*CC + c0)*HH*WW;
    int off[4];
    #pragma unroll
    for (int hj = 0; hj < 4; hj++) off[hj] = (w*8 + hj*2 + sub)*16 + q;

    for (int ci = 0; ci < TC; ci++) {
        // direct loads (TLP hides latency at 4 blocks/SM)
        const float4* p = (const float4*)(xb + (size_t)ci*HH*WW);
        float4 cur[4];
        #pragma unroll
        for (int hj = 0; hj < 4; hj++) cur[hj] = __ldcs(p + off[hj]);

        const float sc = s_scale[ci], sh = s_shift[ci];
        const int buf = ci & 1;
        float4 cmax = make_float4(-INFINITY,-INFINITY,-INFINITY,-INFINITY);
        float4 csum = make_float4(0.f,0.f,0.f,0.f);

        #pragma unroll
        for (int hj = 0; hj < 4; hj++) {
            float4 xn;
            xn.x = fmaf(cur[hj].x, sc, sh); xn.y = fmaf(cur[hj].y, sc, sh);
            xn.z = fmaf(cur[hj].z, sc, sh); xn.w = fmaf(cur[hj].w, sc, sh);

            hmax[hj] = f4max(hmax[hj], xn); hsum[hj] = f4add(hsum[hj], xn);
            cmax     = f4max(cmax, xn);     csum     = f4add(csum, xn);

            // ch partial for (row, q): horizontal fold of this thread's 4 W values
            const int row = w*8 + hj*2 + sub;
            s_ch_max[buf][row][q] = fmaxf(fmaxf(xn.x, xn.y), fmaxf(xn.z, xn.w));
            s_ch_sum[buf][row][q] = (xn.x + xn.y) + (xn.z + xn.w);
        }

        // cw partial for this (warp,sub) row-group
        *(float4*)&s_cw_max[buf][w*2 + sub][q*4] = cmax;
        *(float4*)&s_cw_sum[buf][w*2 + sub][q*4] = csum;

        // every 2 channels: fold staged partials with all 256 threads
        if (buf == 1) {
            __syncthreads();
            if (tid < 128) {
                // ch: (cb, h) -> fold 16 q partials -> smem output staging
                const int cb = tid & 1;
                const int h  = tid >> 1;
                float4 m0 = *(const float4*)&s_ch_max[cb][h][0];
                float4 m1 = *(const float4*)&s_ch_max[cb][h][4];
                float4 m2 = *(const float4*)&s_ch_max[cb][h][8];
                float4 m3 = *(const float4*)&s_ch_max[cb][h][12];
                float4 s0 = *(const float4*)&s_ch_sum[cb][h][0];
                float4 s1 = *(const float4*)&s_ch_sum[cb][h][4];
                float4 s2 = *(const float4*)&s_ch_sum[cb][h][8];
                float4 s3 = *(const float4*)&s_ch_sum[cb][h][12];
                float4 mm = f4max(f4max(m0, m1), f4max(m2, m3));
                float4 ss = f4add(f4add(s0, s1), f4add(s2, s3));
                const int cl = ci - 1 + cb;            // local channel 0..15
                s_cho_max[h][cl] = fmaxf(fmaxf(mm.x, mm.y), fmaxf(mm.z, mm.w));
                s_cho_sum[h][cl] = (ss.x + ss.y) + (ss.z + ss.w);
            } else {
                // cw: (cb, wcol) -> fold 16 row-group partials -> coalesced STG
                const int tt = tid - 128;
                const int cb = tt & 1;
                const int wc = tt >> 1;
                float m = s_cw_max[cb][0][wc];
                float s = s_cw_sum[cb][0][wc];
                #pragma unroll
                for (int k = 1; k < 16; k++) {
                    m = fmaxf(m, s_cw_max[cb][k][wc]);
                    s += s_cw_sum[cb][k][wc];
                }
                size_t idx = ((size_t)b*CC + (c0 + ci - 1 + cb))*WW + wc;
                g_pool_cw_max[idx] = m;
                g_pool_cw_sum[idx] = s;
            }
            __syncthreads();
        }
    }

    // ch writeout: coalesced float4 stores along C (16 channels per row)
    {
        const int hrow = tid >> 2;      // 0..63
        const int f    = tid & 3;       // 0..3 -> channels 4f..4f+3
        float4 mo, so;
        mo.x = s_cho_max[hrow][4*f+0]; mo.y = s_cho_max[hrow][4*f+1];
        mo.z = s_cho_max[hrow][4*f+2]; mo.w = s_cho_max[hrow][4*f+3];
        so.x = s_cho_sum[hrow][4*f+0]; so.y = s_cho_sum[hrow][4*f+1];
        so.z = s_cho_sum[hrow][4*f+2]; so.w = s_cho_sum[hrow][4*f+3];
        size_t idx4 = (((size_t)b*HH + hrow)*CC + c0)/4 + f;
        ((float4*)g_pool_ch_max)[idx4] = mo;
        ((float4*)g_pool_ch_sum)[idx4] = so;
    }

    // hw: plain vector stores of this C-group's partials (no atomics)
    {
        float4* pm4 = (float4*)g_hw_part_max + (size_t)cg * (BB*HH*WW/4);
        float4* ps4 = (float4*)g_hw_part_sum + (size_t)cg * (BB*HH*WW/4);
        #pragma unroll
        for (int hj = 0; hj < 4; hj++) {
            const int h = w*8 + hj*2 + sub;
            size_t idx = ((size_t)b*HH + h)*(WW/4) + q;
            pm4[idx] = hmax[hj];
            ps4[idx] = hsum[hj];
        }
    }
}

// ---- kernel 1b: fold the 16 hw partial planes ----
__global__ __launch_bounds__(256) void hw_reduce_kernel() {
    const int i = blockIdx.x * blockDim.x + threadIdx.x;   // over BHW/4
    const int STRIDE = BB*HH*WW/4;
    const float4* pm4 = (const float4*)g_hw_part_max;
    const float4* ps4 = (const float4*)g_hw_part_sum;

    float4 m = pm4[i];
    float4 s = ps4[i];
    #pragma unroll
    for (int g = 1; g < NCG; g++) {
        m = f4max(m, pm4[(size_t)g*STRIDE + i]);
        s = f4add(s, ps4[(size_t)g*STRIDE + i]);
    }
    ((float4*)g_pool_hw_max)[i] = m;
    ((float4*)g_pool_hw_sum)[i] = s;
}

// ---- kernel 2: ALL three 7x7 conv gates, fused + smem tiled ----
__global__ __launch_bounds__(256) void conv_gate_fused_kernel(
    const float* __restrict__ hw_w, const float* __restrict__ hw_g,
    const float* __restrict__ hw_b, const float* __restrict__ hw_m,
    const float* __restrict__ hw_v,
    const float* __restrict__ cw_w, const float* __restrict__ cw_g,
    const float* __restrict__ cw_b, const float* __restrict__ cw_m,
    const float* __restrict__ cw_v,
    const float* __restrict__ ch_w, const float* __restrict__ ch_g,
    const float* __restrict__ ch_b, const float* __restrict__ ch_m,
    const float* __restrict__ ch_v)
{
    __shared__ float smax[38*39];
    __shared__ float ssum[38*39];
    __shared__ float swt[98];
    __shared__ float sbn[2];

    const int bid = blockIdx.x;
    const int tid = threadIdx.x;

    int R, S, bImg, ti, tj;
    const float *pm, *ps, *wts, *g1, *b1, *m1, *v1;
    float *gate;
    float invN;
    if (bid < 128) {
        R = HH; S = WW; bImg = bid >> 2; int t = bid & 3;
        ti = (t >> 1) * 32; tj = (t & 1) * 32;
        pm = g_pool_hw_max; ps = g_pool_hw_sum; gate = g_gate_hw;
        wts = hw_w; g1 = hw_g; b1 = hw_b; m1 = hw_m; v1 = hw_v; invN = 1.f/256.f;
    } else if (bid < 640) {
        R = CC; S = WW; int t = bid - 128; bImg = t >> 4; t &= 15;
        ti = (t >> 1) * 32; tj = (t & 1) * 32;
        pm = g_pool_cw_max; ps = g_pool_cw_sum; gate = g_gate_cw;
        wts = cw_w; g1 = cw_g; b1 = cw_b; m1 = cw_m; v1 = cw_v; invN = 1.f/64.f;
    } else {
        R = HH; S = CC; int t = bid - 640; bImg = t >> 4; t &= 15;
        ti = (t >> 3) * 32; tj = (t & 7) * 32;
        pm = g_pool_ch_max; ps = g_pool_ch_sum; gate = g_gate_ch;
        wts = ch_w; g1 = ch_g; b1 = ch_b; m1 = ch_m; v1 = ch_v; invN = 1.f/64.f;
    }
    pm += (size_t)bImg * R * S;
    ps += (size_t)bImg * R * S;
    gate += (size_t)bImg * R * S;

    for (int i = tid; i < 38*38; i += 256) {
        int li = i / 38, lj = i - li*38;
        int gi = ti + li - 3, gj = tj + lj - 3;
        bool ok = (gi >= 0) & (gi < R) & (gj >= 0) & (gj < S);
        size_t p = (size_t)gi * S + gj;
        smax[li*39 + lj] = ok ? __ldg(&pm[p]) : 0.f;
        ssum[li*39 + lj] = ok ? __ldg(&ps[p]) : 0.f;
    }
    if (tid < 98) swt[tid] = __ldg(&wts[tid]) * (tid >= 49 ? invN : 1.f);
    if (tid == 98) {
        float s = __ldg(&g1[0]) * rsqrtf(__ldg(&v1[0]) + EPS);
        sbn[0] = s;
        sbn[1] = __ldg(&b1[0]) - __ldg(&m1[0]) * s;
    }
    __syncthreads();

    const int ty = tid >> 3;
    const int tx = (tid & 7) * 4;
    float acc0 = 0.f, acc1 = 0.f, acc2 = 0.f, acc3 = 0.f;

    #pragma unroll
    for (int di = 0; di < 7; di++) {
        float rm[10], rs[10];
        const int rowb = (ty + di) * 39 + tx;
        #pragma unroll
        for (int k = 0; k < 10; k++) {
            rm[k] = smax[rowb + k];
            rs[k] = ssum[rowb + k];
        }
        #pragma unroll
        for (int dj = 0; dj < 7; dj++) {
            const float w1 = swt[di*7 + dj];
            const float w2 = swt[49 + di*7 + dj];
            acc0 = fmaf(rm[dj+0], w1, acc0); acc0 = fmaf(rs[dj+0], w2, acc0);
            acc1 = fmaf(rm[dj+1], w1, acc1); acc1 = fmaf(rs[dj+1], w2, acc1);
            acc2 = fmaf(rm[dj+2], w1, acc2); acc2 = fmaf(rs[dj+2], w2, acc2);
            acc3 = fmaf(rm[dj+3], w1, acc3); acc3 = fmaf(rs[dj+3], w2, acc3);
        }
    }

    const float s = sbn[0], t0 = sbn[1];
    float4 o;
    o.x = 1.f / (1.f + expf(-fmaf(acc0, s, t0)));
    o.y = 1.f / (1.f + expf(-fmaf(acc1, s, t0)));
    o.z = 1.f / (1.f + expf(-fmaf(acc2, s, t0)));
    o.w = 1.f / (1.f + expf(-fmaf(acc3, s, t0)));
    *(float4*)(gate + (size_t)(ti + ty) * S + (tj + tx)) = o;
}

// ---- kernel 3: out = x + (1/3)(g_hw + g_cw + g_ch) * relu(BN(x)) ----
__global__ __launch_bounds__(256) void final_kernel(
    const float* __restrict__ x,
    const float* __restrict__ gamma, const float* __restrict__ beta,
    const float* __restrict__ mean,  const float* __restrict__ var,
    float* __restrict__ out)
{
    size_t t = (size_t)blockIdx.x * blockDim.x + threadIdx.x;
    int w4 = (int)(t & 15);
    int h  = (int)((t >> 4) & 63);
    int c  = (int)((t >> 10) & 255);
    int b  = (int)(t >> 18);

    float4 xv = __ldcs(&((const float4*)x)[t]);   // streaming read

    float sc = __ldg(&gamma[c]) * rsqrtf(__ldg(&var[c]) + EPS);
    float sh = __ldg(&beta[c]) - __ldg(&mean[c]) * sc;

    float4 ghw = __ldg(&((const float4*)g_gate_hw)[((size_t)b*HH + h)*(WW/4) + w4]);
    float4 gcw = __ldg(&((const float4*)g_gate_cw)[((size_t)b*CC + c)*(WW/4) + w4]);
    float  gch = __ldg(&g_gate_ch[((size_t)b*HH + h)*CC + c]);

    const float k = 1.f / 3.f;
    float4 o;
    { float xn = fmaf(xv.x, sc, sh); float l = fmaxf(xn, 0.f);
      o.x = fmaf(k * (ghw.x + gcw.x + gch), l, xv.x); }
    { float xn = fmaf(xv.y, sc, sh); float l = fmaxf(xn, 0.f);
      o.y = fmaf(k * (ghw.y + gcw.y + gch), l, xv.y); }
    { float xn = fmaf(xv.z, sc, sh); float l = fmaxf(xn, 0.f);
      o.z = fmaf(k * (ghw.z + gcw.z + gch), l, xv.z); }
    { float xn = fmaf(xv.w, sc, sh); float l = fmaxf(xn, 0.f);
      o.w = fmaf(k * (ghw.w + gcw.w + gch), l, xv.w); }
    __stcs(&((float4*)out)[t], o);                // streaming write
}

extern "C" void kernel_launch(void* const* d_in, const int* in_sizes, int n_in,
                              void* d_out, int out_size) {
    const float* x     = (const float*)d_in[0];
    const float* gamma = (const float*)d_in[1];
    const float* beta  = (const float*)d_in[2];
    const float* mean  = (const float*)d_in[3];
    const float* var   = (const float*)d_in[4];
    const float* hw_w  = (const float*)d_in[5];
    const float* hw_g  = (const float*)d_in[6];
    const float* hw_b  = (const float*)d_in[7];
    const float* hw_m  = (const float*)d_in[8];
    const float* hw_v  = (const float*)d_in[9];
    const float* cw_w  = (const float*)d_in[10];
    const float* cw_g  = (const float*)d_in[11];
    const float* cw_b  = (const float*)d_in[12];
    const float* cw_m  = (const float*)d_in[13];
    const float* cw_v  = (const float*)d_in[14];
    const float* ch_w  = (const float*)d_in[15];
    const float* ch_g  = (const float*)d_in[16];
    const float* ch_b  = (const float*)d_in[17];
    const float* ch_m  = (const float*)d_in[18];
    const float* ch_v  = (const float*)d_in[19];
    float* out = (float*)d_out;

    // 1) fused BN + triple pooling
    dim3 pg(CC/TC, BB);
    pool_kernel<<<pg, 256>>>(x, gamma, beta, mean, var);

    // 1b) fold hw partials
    hw_reduce_kernel<<<(BB*HH*WW/4)/256, 256>>>();

    // 2) all three conv gates in one launch
    conv_gate_fused_kernel<<<1152, 256>>>(
        hw_w, hw_g, hw_b, hw_m, hw_v,
        cw_w, cw_g, cw_b, cw_m, cw_v,
        ch_w, ch_g, ch_b, ch_m, ch_v);

    // 3) final fused elementwise
    size_t total4 = (size_t)BB*CC*HH*WW/4;
    final_kernel<<<(unsigned)(total4/256), 256>>>(
        x, gamma, beta, mean, var, out);
}